// round 8
// baseline (speedup 1.0000x reference)
#include <cuda_runtime.h>
#include <cuda_fp16.h>
#include <cstdint>

#define NMAX 100000
#define EMAX 1600000
#define HID  64
#define INCH 128

// ---------------- scratch (static device globals; no allocation) ----------------
__device__ __align__(256) __half g_Ph[(size_t)NMAX * HID]; // h @ w_rel (fp16 messages)
__device__ __align__(256) float  g_B[(size_t)NMAX * HID];  // h @ w_root + b_rel
__device__ __align__(256) float  g_H[(size_t)NMAX * HID];  // activations
__device__ int   g_col[EMAX];          // CSR column (src) array
__device__ int   g_deg[NMAX];
__device__ int   g_rowptr[NMAX + 1];
__device__ int   g_cursor[NMAX];
__device__ int   g_batch[NMAX];
__device__ int   g_bsum[256];
__device__ int   g_boff[256];
__device__ float g_gsum[64 * HID];
__device__ int   g_flag64;             // 1 if edge_index/batch stored as int64

// ---------------- f32x2 packed-FMA helpers (ptxas never emits FFMA2 from C++) ----
__device__ __forceinline__ unsigned long long pack2(float lo, float hi) {
    unsigned long long r;
    asm("mov.b64 %0, {%1, %2};" : "=l"(r) : "f"(lo), "f"(hi));
    return r;
}
__device__ __forceinline__ void ffma2(unsigned long long& d,
                                      unsigned long long a, unsigned long long b) {
    asm("fma.rn.f32x2 %0, %1, %2, %0;" : "+l"(d) : "l"(a), "l"(b));
}
__device__ __forceinline__ void unpack2(unsigned long long v, float& lo, float& hi) {
    asm("mov.b64 {%0, %1}, %2;" : "=f"(lo), "=f"(hi) : "l"(v));
}

// ---------------- dtype detection ----------------
__global__ void k_detect(const int* e32) {
    __shared__ int any;
    if (threadIdx.x == 0) any = 0;
    __syncthreads();
    int v = 0;
    // int64: every odd 32-bit word (high half) is 0 (values < 1e5).
    // int32: odd words are random node indices — nonzero w.h.p.
    for (int i = threadIdx.x; i < 1024; i += blockDim.x) v |= e32[2 * i + 1];
    if (v) atomicOr(&any, 1);
    __syncthreads();
    if (threadIdx.x == 0) g_flag64 = (any == 0) ? 1 : 0;
}

// ---------------- zero scratch + batch conversion (merged) ----------------
__global__ void k_prep(const void* braw, int n) {
    int i = blockIdx.x * blockDim.x + threadIdx.x;
    if (i < n) {
        g_deg[i] = 0;
        g_batch[i] = g_flag64 ? (int)((const long long*)braw)[i] : ((const int*)braw)[i];
    }
    if (i < 64 * HID) g_gsum[i] = 0.f;
}

// ---------------- degree histogram straight from raw input ----------------
__global__ void k_hist(const void* eraw, int e) {
    int i = blockIdx.x * blockDim.x + threadIdx.x;
    if (i >= e) return;
    int d = g_flag64 ? (int)((const long long*)eraw)[(size_t)e + i]
                     : ((const int*)eraw)[e + i];
    atomicAdd(&g_deg[d], 1);
}

// ---------------- 3-kernel exclusive scan over degrees ----------------
__global__ void k_scan1(int n) {
    __shared__ int s[1024];
    int i = blockIdx.x * 1024 + threadIdx.x;
    int v = (i < n) ? g_deg[i] : 0;
    s[threadIdx.x] = v;
    __syncthreads();
#pragma unroll
    for (int off = 1; off < 1024; off <<= 1) {
        int t = (threadIdx.x >= (unsigned)off) ? s[threadIdx.x - off] : 0;
        __syncthreads();
        s[threadIdx.x] += t;
        __syncthreads();
    }
    if (i < n) g_rowptr[i] = s[threadIdx.x] - v;   // exclusive within block
    if (threadIdx.x == 1023) g_bsum[blockIdx.x] = s[1023];
}

__global__ void k_scan2(int nb) {
    if (threadIdx.x == 0 && blockIdx.x == 0) {
        int run = 0;
        for (int b = 0; b < nb; b++) { int t = g_bsum[b]; g_boff[b] = run; run += t; }
    }
}

__global__ void k_scan3(int n, int e) {
    int i = blockIdx.x * 1024 + threadIdx.x;
    if (i < n) {
        int v = g_rowptr[i] + g_boff[blockIdx.x];
        g_rowptr[i] = v;
        g_cursor[i] = v;
    }
    if (i == 0) g_rowptr[n] = e;
}

__global__ void k_fill(const void* eraw, int e) {
    int i = blockIdx.x * blockDim.x + threadIdx.x;
    if (i >= e) return;
    int s, d;
    if (g_flag64) {
        const long long* p = (const long long*)eraw;
        s = (int)p[i];
        d = (int)p[(size_t)e + i];
    } else {
        const int* p = (const int*)eraw;
        s = p[i];
        d = p[e + i];
    }
    int pos = atomicAdd(&g_cursor[d], 1);
    g_col[pos] = s;
}

// ---------------- dual GEMM: P(fp16) = X @ Wrel ; B = X @ Wroot + b_rel ----------
// 256 threads, 64-row tile; each thread: 4 rows x 8 cols via f32x2 packed FMA.
template <int K>
__global__ __launch_bounds__(256) void k_gemm_dual(
    const float* __restrict__ X,
    const float* __restrict__ Wrel,
    const float* __restrict__ Wroot,
    const float* __restrict__ brel,
    int n)
{
    extern __shared__ float sm[];
    float* Ws = sm;                // [K][128]: cols 0-63 = Wrel, 64-127 = Wroot
    float* Hs = sm + K * 128;      // [64][K]
    const float* src = (K == INCH) ? X : g_H;

    int tid = threadIdx.x;
    int row0 = blockIdx.x * 64;

    for (int i = tid; i < K * 64; i += 256) {
        int k = i >> 6, c = i & 63;
        Ws[k * 128 + c]      = Wrel[i];
        Ws[k * 128 + 64 + c] = Wroot[i];
    }
    for (int i = tid; i < (64 * K) / 4; i += 256) {
        int el = i * 4;
        int r = el / K, kk = el % K;
        int gr = row0 + r;
        float4 v = make_float4(0.f, 0.f, 0.f, 0.f);
        if (gr < n) v = *(const float4*)(src + (size_t)gr * K + kk);
        *(float4*)(Hs + r * K + kk) = v;
    }
    __syncthreads();

    int tx = tid & 15, ty = tid >> 4;
    int c0 = tx * 4;          // 4 contiguous cols in each half (conflict-free LDS.128)
    int r0 = ty * 4;

    // acc2[row][pair]: pair 0=(c0,c0+1)rel 1=(c0+2,c0+3)rel 2,3 = same in root half
    unsigned long long acc2[4][4];
#pragma unroll
    for (int i = 0; i < 4; i++)
#pragma unroll
        for (int j = 0; j < 4; j++) acc2[i][j] = 0ull;

#pragma unroll 8
    for (int k = 0; k < K; k++) {
        unsigned long long pa[4];
#pragma unroll
        for (int i = 0; i < 4; i++) {
            float a = Hs[(r0 + i) * K + k];
            pa[i] = pack2(a, a);
        }
        float4 b0 = *(float4*)&Ws[k * 128 + c0];        // Wrel cols
        float4 b1 = *(float4*)&Ws[k * 128 + 64 + c0];   // Wroot cols
        unsigned long long pb[4];
        pb[0] = pack2(b0.x, b0.y);
        pb[1] = pack2(b0.z, b0.w);
        pb[2] = pack2(b1.x, b1.y);
        pb[3] = pack2(b1.z, b1.w);
#pragma unroll
        for (int i = 0; i < 4; i++) {
            ffma2(acc2[i][0], pa[i], pb[0]);
            ffma2(acc2[i][1], pa[i], pb[1]);
            ffma2(acc2[i][2], pa[i], pb[2]);
            ffma2(acc2[i][3], pa[i], pb[3]);
        }
    }

    float bb0 = brel[c0 + 0], bb1 = brel[c0 + 1], bb2 = brel[c0 + 2], bb3 = brel[c0 + 3];
#pragma unroll
    for (int i = 0; i < 4; i++) {
        int gr = row0 + r0 + i;
        if (gr >= n) continue;
        float p0, p1, p2, p3, q0, q1, q2, q3;
        unpack2(acc2[i][0], p0, p1);
        unpack2(acc2[i][1], p2, p3);
        unpack2(acc2[i][2], q0, q1);
        unpack2(acc2[i][3], q2, q3);
        __half2 h01 = __floats2half2_rn(p0, p1);
        __half2 h23 = __floats2half2_rn(p2, p3);
        __half2* pdst = (__half2*)(g_Ph + (size_t)gr * 64 + c0);
        pdst[0] = h01;
        pdst[1] = h23;
        *(float4*)(g_B + (size_t)gr * 64 + c0) =
            make_float4(q0 + bb0, q1 + bb1, q2 + bb2, q3 + bb3);
    }
}

// ---------------- pull aggregation: H[i] = relu(B[i] + sum_{j in N(i)} Ph[j]) ----
// ONE WARP PER NODE: uniform degree loop (no intra-warp divergence),
// one half2 (4B) per lane -> one coalesced 128B line per edge.
__global__ __launch_bounds__(256) void k_agg(int n) {
    int w = (blockIdx.x * blockDim.x + threadIdx.x) >> 5;
    int lane = threadIdx.x & 31;
    if (w >= n) return;
    const __half2* P2 = (const __half2*)g_Ph;
    int beg = g_rowptr[w], end = g_rowptr[w + 1];
    float2 acc = *(const float2*)(g_B + (size_t)w * 64 + lane * 2);
    int j = beg;
    for (; j + 3 < end; j += 4) {
        int s0 = g_col[j], s1 = g_col[j + 1], s2 = g_col[j + 2], s3 = g_col[j + 3];
        float2 f0 = __half22float2(P2[(size_t)s0 * 32 + lane]);
        float2 f1 = __half22float2(P2[(size_t)s1 * 32 + lane]);
        float2 f2 = __half22float2(P2[(size_t)s2 * 32 + lane]);
        float2 f3 = __half22float2(P2[(size_t)s3 * 32 + lane]);
        acc.x += (f0.x + f1.x) + (f2.x + f3.x);
        acc.y += (f0.y + f1.y) + (f2.y + f3.y);
    }
    for (; j < end; j++) {
        float2 f = __half22float2(P2[(size_t)g_col[j] * 32 + lane]);
        acc.x += f.x; acc.y += f.y;
    }
    acc.x = fmaxf(acc.x, 0.f);
    acc.y = fmaxf(acc.y, 0.f);
    *(float2*)(g_H + (size_t)w * 64 + lane * 2) = acc;
}

// ---------------- pooling: run-length accumulate (batch is sorted), few atomics --
__global__ __launch_bounds__(256) void k_pool(int n) {
    int d = threadIdx.x & 63;
    int s = threadIdx.x >> 6;      // 0..3
    int start = blockIdx.x * 1024;
    int endn = min(start + 1024, n);
    float acc = 0.f;
    int curg = -1;
    for (int node = start + s; node < endn; node += 4) {
        int g = g_batch[node];
        if (g != curg) {
            if (curg >= 0) atomicAdd(&g_gsum[curg * 64 + d], acc);
            acc = 0.f; curg = g;
        }
        acc += g_H[(size_t)node * 64 + d];
    }
    if (curg >= 0) atomicAdd(&g_gsum[curg * 64 + d], acc);
}

// ---------------- MLP head (graph counts computed in-block) ----------------
__global__ __launch_bounds__(256) void k_head(
    const float* __restrict__ W1, const float* __restrict__ b1,
    const float* __restrict__ W2, const float* __restrict__ b2,
    float* __restrict__ out, int n)
{
    __shared__ float pm[64 * 64];
    __shared__ float w1s[64 * 64];
    __shared__ float z[64 * 64];
    __shared__ int   cnt[64];
    int tid = threadIdx.x;
    if (tid < 64) {
        int g = tid;
        int lo0 = 0, hi = n;
        while (lo0 < hi) { int m = (lo0 + hi) >> 1; if (g_batch[m] < g) lo0 = m + 1; else hi = m; }
        int lo1 = lo0; hi = n;
        while (lo1 < hi) { int m = (lo1 + hi) >> 1; if (g_batch[m] < g + 1) lo1 = m + 1; else hi = m; }
        cnt[g] = lo1 - lo0;
    }
    __syncthreads();
    for (int i = tid; i < 4096; i += 256) {
        int g = i >> 6;
        pm[i] = g_gsum[i] / fmaxf((float)cnt[g], 1.f);
        w1s[i] = W1[i];
    }
    __syncthreads();
    for (int idx = tid; idx < 4096; idx += 256) {
        int g = idx >> 6, jj = idx & 63;
        float s = b1[jj];
#pragma unroll 8
        for (int k = 0; k < 64; k++) s = fmaf(pm[g * 64 + k], w1s[k * 64 + jj], s);
        z[idx] = fmaxf(s, 0.f);
    }
    __syncthreads();
    if (tid < 128) {
        int g = tid >> 1, o = tid & 1;
        float s = b2[o];
#pragma unroll 8
        for (int jj = 0; jj < 64; jj++) s = fmaf(z[g * 64 + jj], W2[jj * 2 + o], s);
        out[g * 2 + o] = s;
    }
}

// ---------------- launch ----------------
extern "C" void kernel_launch(void* const* d_in, const int* in_sizes, int n_in,
                              void* d_out, int out_size)
{
    const float* x      = (const float*)d_in[0];
    const void*  eidx   = d_in[1];
    const void*  batch  = d_in[2];
    const float* wr0    = (const float*)d_in[3];
    const float* br0    = (const float*)d_in[4];
    const float* wroot0 = (const float*)d_in[5];
    const float* wr1    = (const float*)d_in[6];
    const float* br1    = (const float*)d_in[7];
    const float* wroot1 = (const float*)d_in[8];
    const float* wr2    = (const float*)d_in[9];
    const float* br2    = (const float*)d_in[10];
    const float* wroot2 = (const float*)d_in[11];
    const float* hw1    = (const float*)d_in[12];
    const float* hb1    = (const float*)d_in[13];
    const float* hw2    = (const float*)d_in[14];
    const float* hb2    = (const float*)d_in[15];

    int n = in_sizes[0] / INCH;    // 100000
    int e = in_sizes[1] / 2;       // 1600000 (element count is dtype-independent)

    cudaFuncSetAttribute(k_gemm_dual<INCH>, cudaFuncAttributeMaxDynamicSharedMemorySize,
                         INCH * 192 * 4);
    cudaFuncSetAttribute(k_gemm_dual<HID>, cudaFuncAttributeMaxDynamicSharedMemorySize,
                         HID * 192 * 4);

    k_detect<<<1, 256>>>((const int*)eidx);
    k_prep<<<(n + 255) / 256, 256>>>(batch, n);
    k_hist<<<(e + 255) / 256, 256>>>(eidx, e);

    int nb = (n + 1023) / 1024;
    k_scan1<<<nb, 1024>>>(n);
    k_scan2<<<1, 32>>>(nb);
    k_scan3<<<nb, 1024>>>(n, e);
    k_fill<<<(e + 255) / 256, 256>>>(eidx, e);

    int gb = (n + 63) / 64;
    int ab = (n * 32 + 255) / 256;   // one warp per node

    // Layer 0 (K=128 input)
    k_gemm_dual<INCH><<<gb, 256, INCH * 192 * 4>>>(x, wr0, wroot0, br0, n);
    k_agg<<<ab, 256>>>(n);
    // Layer 1
    k_gemm_dual<HID><<<gb, 256, HID * 192 * 4>>>(nullptr, wr1, wroot1, br1, n);
    k_agg<<<ab, 256>>>(n);
    // Layer 2
    k_gemm_dual<HID><<<gb, 256, HID * 192 * 4>>>(nullptr, wr2, wroot2, br2, n);
    k_agg<<<ab, 256>>>(n);

    k_pool<<<(n + 1023) / 1024, 256>>>(n);
    k_head<<<1, 256>>>(hw1, hb1, hw2, hb2, (float*)d_out, n);
}

// round 11
// speedup vs baseline: 1.0232x; 1.0232x over previous
#include <cuda_runtime.h>
#include <cstdint>

#define NMAX 100000
#define EMAX 1600000
#define HID  64
#define INCH 128

// ---------------- scratch (static device globals; no allocation) ----------------
__device__ __align__(256) float g_P[(size_t)NMAX * HID];   // h @ w_rel
__device__ __align__(256) float g_B[(size_t)NMAX * HID];   // h @ w_root + b_rel
__device__ __align__(256) float g_H[(size_t)NMAX * HID];   // activations
__device__ int   g_col[EMAX];          // CSR column (src) array
__device__ int   g_deg[NMAX];
__device__ int   g_rowptr[NMAX + 1];
__device__ int   g_cursor[NMAX];
__device__ int   g_batch[NMAX];
__device__ float g_gsum[64 * HID];

// ---------------- f32x2 packed-FMA helpers (ptxas never emits FFMA2 from C++) ----
__device__ __forceinline__ unsigned long long pack2(float lo, float hi) {
    unsigned long long r;
    asm("mov.b64 %0, {%1, %2};" : "=l"(r) : "f"(lo), "f"(hi));
    return r;
}
__device__ __forceinline__ void ffma2(unsigned long long& d,
                                      unsigned long long a, unsigned long long b) {
    asm("fma.rn.f32x2 %0, %1, %2, %0;" : "+l"(d) : "l"(a), "l"(b));
}
__device__ __forceinline__ void unpack2(unsigned long long v, float& lo, float& hi) {
    asm("mov.b64 {%0, %1}, %2;" : "=f"(lo), "=f"(hi) : "l"(v));
}

// ---------------- inline dtype detection (no separate kernel, no global flag) ----
// int64: odd 32-bit words (high halves) are 0 (all values < 1e5).
// int32: odd words are random node ids — 64 consecutive zeros has p ~ 1e-320.
__device__ __forceinline__ int detect_is64(const int* e32) {
    int lane = threadIdx.x & 31;
    int v = e32[2 * lane + 1] | e32[2 * (lane + 32) + 1];
    return __all_sync(0xffffffffu, v == 0) ? 1 : 0;
}

// ---------------- zero scratch + batch conversion (merged) ----------------
__global__ void k_prep(const void* braw, const int* e32, int n) {
    int is64 = detect_is64(e32);
    int i = blockIdx.x * blockDim.x + threadIdx.x;
    if (i < n) {
        g_deg[i] = 0;
        g_batch[i] = is64 ? (int)((const long long*)braw)[i] : ((const int*)braw)[i];
    }
    if (i < 64 * HID) g_gsum[i] = 0.f;
}

// ---------------- degree histogram straight from raw input ----------------
__global__ void k_hist(const void* eraw, int e) {
    int is64 = detect_is64((const int*)eraw);
    int i = blockIdx.x * blockDim.x + threadIdx.x;
    if (i >= e) return;
    int d = is64 ? (int)((const long long*)eraw)[(size_t)e + i]
                 : ((const int*)eraw)[e + i];
    atomicAdd(&g_deg[d], 1);
}

// ---------------- single-block exclusive scan over degrees (replaces 3 kernels) --
__global__ __launch_bounds__(1024) void k_scan(int n, int e) {
    __shared__ int psum[1024];
    const int CH = (n + 1023) / 1024;
    int t = threadIdx.x;
    int lo = t * CH, hi = min(lo + CH, n);
    int s = 0;
    for (int i = lo; i < hi; i++) s += g_deg[i];
    psum[t] = s;
    __syncthreads();
#pragma unroll
    for (int off = 1; off < 1024; off <<= 1) {
        int v = (t >= off) ? psum[t - off] : 0;
        __syncthreads();
        psum[t] += v;
        __syncthreads();
    }
    int base = (t == 0) ? 0 : psum[t - 1];
    for (int i = lo; i < hi; i++) {
        int d = g_deg[i];
        g_rowptr[i] = base;
        g_cursor[i] = base;
        base += d;
    }
    if (t == 1023) g_rowptr[n] = e;
}

__global__ void k_fill(const void* eraw, int e) {
    int is64 = detect_is64((const int*)eraw);
    int i = blockIdx.x * blockDim.x + threadIdx.x;
    if (i >= e) return;
    int s, d;
    if (is64) {
        const long long* p = (const long long*)eraw;
        s = (int)p[i];
        d = (int)p[(size_t)e + i];
    } else {
        const int* p = (const int*)eraw;
        s = p[i];
        d = p[e + i];
    }
    int pos = atomicAdd(&g_cursor[d], 1);
    g_col[pos] = s;
}

// ---------------- dual GEMM: P = X @ Wrel ; B = X @ Wroot + b_rel ----------------
// 256 threads, 64-row tile; each thread: 4 rows x 8 cols via f32x2 packed FMA.
template <int K>
__global__ __launch_bounds__(256) void k_gemm_dual(
    const float* __restrict__ X,
    const float* __restrict__ Wrel,
    const float* __restrict__ Wroot,
    const float* __restrict__ brel,
    int n)
{
    extern __shared__ float sm[];
    float* Ws = sm;                // [K][128]: cols 0-63 = Wrel, 64-127 = Wroot
    float* Hs = sm + K * 128;      // [64][K]
    const float* src = (K == INCH) ? X : g_H;

    int tid = threadIdx.x;
    int row0 = blockIdx.x * 64;

    for (int i = tid; i < K * 64; i += 256) {
        int k = i >> 6, c = i & 63;
        Ws[k * 128 + c]      = Wrel[i];
        Ws[k * 128 + 64 + c] = Wroot[i];
    }
    for (int i = tid; i < (64 * K) / 4; i += 256) {
        int el = i * 4;
        int r = el / K, kk = el % K;
        int gr = row0 + r;
        float4 v = make_float4(0.f, 0.f, 0.f, 0.f);
        if (gr < n) v = *(const float4*)(src + (size_t)gr * K + kk);
        *(float4*)(Hs + r * K + kk) = v;
    }
    __syncthreads();

    int tx = tid & 15, ty = tid >> 4;
    int c0 = tx * 4;          // 4 contiguous cols in each half (conflict-free LDS.128)
    int r0 = ty * 4;

    // acc2[row][pair]: pair 0=(c0,c0+1)rel 1=(c0+2,c0+3)rel 2,3 = same in root half
    unsigned long long acc2[4][4];
#pragma unroll
    for (int i = 0; i < 4; i++)
#pragma unroll
        for (int j = 0; j < 4; j++) acc2[i][j] = 0ull;

#pragma unroll 8
    for (int k = 0; k < K; k++) {
        unsigned long long pa[4];
#pragma unroll
        for (int i = 0; i < 4; i++) {
            float a = Hs[(r0 + i) * K + k];
            pa[i] = pack2(a, a);
        }
        float4 b0 = *(float4*)&Ws[k * 128 + c0];        // Wrel cols
        float4 b1 = *(float4*)&Ws[k * 128 + 64 + c0];   // Wroot cols
        unsigned long long pb[4];
        pb[0] = pack2(b0.x, b0.y);
        pb[1] = pack2(b0.z, b0.w);
        pb[2] = pack2(b1.x, b1.y);
        pb[3] = pack2(b1.z, b1.w);
#pragma unroll
        for (int i = 0; i < 4; i++) {
            ffma2(acc2[i][0], pa[i], pb[0]);
            ffma2(acc2[i][1], pa[i], pb[1]);
            ffma2(acc2[i][2], pa[i], pb[2]);
            ffma2(acc2[i][3], pa[i], pb[3]);
        }
    }

    float bb0 = brel[c0 + 0], bb1 = brel[c0 + 1], bb2 = brel[c0 + 2], bb3 = brel[c0 + 3];
#pragma unroll
    for (int i = 0; i < 4; i++) {
        int gr = row0 + r0 + i;
        if (gr >= n) continue;
        float p0, p1, p2, p3, q0, q1, q2, q3;
        unpack2(acc2[i][0], p0, p1);
        unpack2(acc2[i][1], p2, p3);
        unpack2(acc2[i][2], q0, q1);
        unpack2(acc2[i][3], q2, q3);
        *(float4*)(g_P + (size_t)gr * 64 + c0) = make_float4(p0, p1, p2, p3);
        *(float4*)(g_B + (size_t)gr * 64 + c0) =
            make_float4(q0 + bb0, q1 + bb1, q2 + bb2, q3 + bb3);
    }
}

// ---------------- pull aggregation: H[i] = relu(B[i] + sum_{j in N(i)} P[j]) ----
// 16 threads per node, float4 per thread. P (25.6MB) is L2-resident.
// (R7 configuration — measured best; R8's fp16/warp-per-node variant regressed.)
__global__ __launch_bounds__(256) void k_agg(int n) {
    int t = blockIdx.x * blockDim.x + threadIdx.x;
    int gid = t >> 4;
    int l4 = (t & 15) * 4;
    if (gid >= n) return;
    int beg = g_rowptr[gid], end = g_rowptr[gid + 1];
    float4 acc = *(const float4*)(g_B + (size_t)gid * 64 + l4);
    int j = beg;
    for (; j + 3 < end; j += 4) {
        int s0 = g_col[j], s1 = g_col[j + 1], s2 = g_col[j + 2], s3 = g_col[j + 3];
        float4 v0 = *(const float4*)(g_P + (size_t)s0 * 64 + l4);
        float4 v1 = *(const float4*)(g_P + (size_t)s1 * 64 + l4);
        float4 v2 = *(const float4*)(g_P + (size_t)s2 * 64 + l4);
        float4 v3 = *(const float4*)(g_P + (size_t)s3 * 64 + l4);
        acc.x += (v0.x + v1.x) + (v2.x + v3.x);
        acc.y += (v0.y + v1.y) + (v2.y + v3.y);
        acc.z += (v0.z + v1.z) + (v2.z + v3.z);
        acc.w += (v0.w + v1.w) + (v2.w + v3.w);
    }
    for (; j < end; j++) {
        int s = g_col[j];
        float4 v = *(const float4*)(g_P + (size_t)s * 64 + l4);
        acc.x += v.x; acc.y += v.y; acc.z += v.z; acc.w += v.w;
    }
    acc.x = fmaxf(acc.x, 0.f);
    acc.y = fmaxf(acc.y, 0.f);
    acc.z = fmaxf(acc.z, 0.f);
    acc.w = fmaxf(acc.w, 0.f);
    *(float4*)(g_H + (size_t)gid * 64 + l4) = acc;
}

// ---------------- pooling: run-length accumulate (batch is sorted), few atomics --
__global__ __launch_bounds__(256) void k_pool(int n) {
    int d = threadIdx.x & 63;
    int s = threadIdx.x >> 6;      // 0..3
    int start = blockIdx.x * 1024;
    int endn = min(start + 1024, n);
    float acc = 0.f;
    int curg = -1;
    for (int node = start + s; node < endn; node += 4) {
        int g = g_batch[node];
        if (g != curg) {
            if (curg >= 0) atomicAdd(&g_gsum[curg * 64 + d], acc);
            acc = 0.f; curg = g;
        }
        acc += g_H[(size_t)node * 64 + d];
    }
    if (curg >= 0) atomicAdd(&g_gsum[curg * 64 + d], acc);
}

// ---------------- MLP head (graph counts computed in-block) ----------------
__global__ __launch_bounds__(256) void k_head(
    const float* __restrict__ W1, const float* __restrict__ b1,
    const float* __restrict__ W2, const float* __restrict__ b2,
    float* __restrict__ out, int n)
{
    __shared__ float pm[64 * 64];
    __shared__ float w1s[64 * 64];
    __shared__ float z[64 * 64];
    __shared__ int   cnt[64];
    int tid = threadIdx.x;
    if (tid < 64) {
        int g = tid;
        int lo0 = 0, hi = n;
        while (lo0 < hi) { int m = (lo0 + hi) >> 1; if (g_batch[m] < g) lo0 = m + 1; else hi = m; }
        int lo1 = lo0; hi = n;
        while (lo1 < hi) { int m = (lo1 + hi) >> 1; if (g_batch[m] < g + 1) lo1 = m + 1; else hi = m; }
        cnt[g] = lo1 - lo0;
    }
    __syncthreads();
    for (int i = tid; i < 4096; i += 256) {
        int g = i >> 6;
        pm[i] = g_gsum[i] / fmaxf((float)cnt[g], 1.f);
        w1s[i] = W1[i];
    }
    __syncthreads();
    for (int idx = tid; idx < 4096; idx += 256) {
        int g = idx >> 6, jj = idx & 63;
        float s = b1[jj];
#pragma unroll 8
        for (int k = 0; k < 64; k++) s = fmaf(pm[g * 64 + k], w1s[k * 64 + jj], s);
        z[idx] = fmaxf(s, 0.f);
    }
    __syncthreads();
    if (tid < 128) {
        int g = tid >> 1, o = tid & 1;
        float s = b2[o];
#pragma unroll 8
        for (int jj = 0; jj < 64; jj++) s = fmaf(z[g * 64 + jj], W2[jj * 2 + o], s);
        out[g * 2 + o] = s;
    }
}

// ---------------- launch ----------------
extern "C" void kernel_launch(void* const* d_in, const int* in_sizes, int n_in,
                              void* d_out, int out_size)
{
    const float* x      = (const float*)d_in[0];
    const void*  eidx   = d_in[1];
    const void*  batch  = d_in[2];
    const float* wr0    = (const float*)d_in[3];
    const float* br0    = (const float*)d_in[4];
    const float* wroot0 = (const float*)d_in[5];
    const float* wr1    = (const float*)d_in[6];
    const float* br1    = (const float*)d_in[7];
    const float* wroot1 = (const float*)d_in[8];
    const float* wr2    = (const float*)d_in[9];
    const float* br2    = (const float*)d_in[10];
    const float* wroot2 = (const float*)d_in[11];
    const float* hw1    = (const float*)d_in[12];
    const float* hb1    = (const float*)d_in[13];
    const float* hw2    = (const float*)d_in[14];
    const float* hb2    = (const float*)d_in[15];

    int n = in_sizes[0] / INCH;    // 100000
    int e = in_sizes[1] / 2;       // 1600000 (element count is dtype-independent)

    cudaFuncSetAttribute(k_gemm_dual<INCH>, cudaFuncAttributeMaxDynamicSharedMemorySize,
                         INCH * 192 * 4);
    cudaFuncSetAttribute(k_gemm_dual<HID>, cudaFuncAttributeMaxDynamicSharedMemorySize,
                         HID * 192 * 4);

    k_prep<<<(n + 255) / 256, 256>>>(batch, (const int*)eidx, n);
    k_hist<<<(e + 255) / 256, 256>>>(eidx, e);
    k_scan<<<1, 1024>>>(n, e);
    k_fill<<<(e + 255) / 256, 256>>>(eidx, e);

    int gb = (n + 63) / 64;
    int ab = ((n * 16) + 255) / 256;   // 16 threads per node (R7 config)

    // Layer 0 (K=128 input)
    k_gemm_dual<INCH><<<gb, 256, INCH * 192 * 4>>>(x, wr0, wroot0, br0, n);
    k_agg<<<ab, 256>>>(n);
    // Layer 1
    k_gemm_dual<HID><<<gb, 256, HID * 192 * 4>>>(nullptr, wr1, wroot1, br1, n);
    k_agg<<<ab, 256>>>(n);
    // Layer 2
    k_gemm_dual<HID><<<gb, 256, HID * 192 * 4>>>(nullptr, wr2, wroot2, br2, n);
    k_agg<<<ab, 256>>>(n);

    k_pool<<<(n + 1023) / 1024, 256>>>(n);
    k_head<<<1, 256>>>(hw1, hb1, hw2, hb2, (float*)d_out, n);
}

// round 15
// speedup vs baseline: 1.4180x; 1.3859x over previous
#include <cuda_runtime.h>
#include <cstdint>

#define NMAX 100000
#define EMAX 1600000
#define HID  64
#define INCH 128

// ---------------- scratch (static device globals; no allocation) ----------------
__device__ __align__(256) float g_P[(size_t)NMAX * HID];   // h @ w_rel
__device__ __align__(256) float g_B[(size_t)NMAX * HID];   // h @ w_root + b_rel
__device__ __align__(256) float g_H[(size_t)NMAX * HID];   // activations
__device__ int   g_col[EMAX];          // CSR column (src) array
__device__ int   g_deg[NMAX];
__device__ int   g_rowptr[NMAX + 1];
__device__ int   g_cursor[NMAX];
__device__ int   g_batch[NMAX];
__device__ int   g_bsum[256];
__device__ int   g_boff[256];
__device__ float g_gsum[64 * HID];
__device__ int   g_gcnt[64];
__device__ int   g_flag64;             // 1 if edge_index/batch stored as int64

// ---------------- tf32 helpers ----------------
__device__ __forceinline__ float to_tf32(float x) {
    float r;
    asm("cvt.rna.tf32.f32 %0, %1;" : "=f"(r) : "f"(x));
    return r;
}
__device__ __forceinline__ void mma_tf32(float c[4],
                                         uint32_t a0, uint32_t a1, uint32_t a2, uint32_t a3,
                                         uint32_t b0, uint32_t b1) {
    asm volatile(
        "mma.sync.aligned.m16n8k8.row.col.f32.tf32.tf32.f32 "
        "{%0,%1,%2,%3}, {%4,%5,%6,%7}, {%8,%9}, {%0,%1,%2,%3};"
        : "+f"(c[0]), "+f"(c[1]), "+f"(c[2]), "+f"(c[3])
        : "r"(a0), "r"(a1), "r"(a2), "r"(a3), "r"(b0), "r"(b1));
}

// ---------------- dtype detection ----------------
__global__ void k_detect(const int* e32) {
    __shared__ int any;
    if (threadIdx.x == 0) any = 0;
    __syncthreads();
    int v = 0;
    // int64: every odd 32-bit word (high half) is 0 (values < 1e5).
    // int32: odd words are random node indices — nonzero w.h.p.
    for (int i = threadIdx.x; i < 1024; i += blockDim.x) v |= e32[2 * i + 1];
    if (v) atomicOr(&any, 1);
    __syncthreads();
    if (threadIdx.x == 0) g_flag64 = (any == 0) ? 1 : 0;
}

// ---------------- zero scratch that accumulates ----------------
__global__ void k_zero(int n) {
    int i = blockIdx.x * blockDim.x + threadIdx.x;
    if (i < n) g_deg[i] = 0;
    if (i < 64 * HID) g_gsum[i] = 0.f;
}

// ---------------- degree histogram straight from raw input ----------------
__global__ void k_hist(const void* eraw, int e) {
    int i = blockIdx.x * blockDim.x + threadIdx.x;
    if (i >= e) return;
    int d = g_flag64 ? (int)((const long long*)eraw)[(size_t)e + i]
                     : ((const int*)eraw)[e + i];
    atomicAdd(&g_deg[d], 1);
}

__global__ void k_convert_batch(const void* braw, int n) {
    int i = blockIdx.x * blockDim.x + threadIdx.x;
    if (i >= n) return;
    g_batch[i] = g_flag64 ? (int)((const long long*)braw)[i] : ((const int*)braw)[i];
}

// ---------------- 3-kernel exclusive scan over degrees ----------------
__global__ void k_scan1(int n) {
    __shared__ int s[1024];
    int i = blockIdx.x * 1024 + threadIdx.x;
    int v = (i < n) ? g_deg[i] : 0;
    s[threadIdx.x] = v;
    __syncthreads();
#pragma unroll
    for (int off = 1; off < 1024; off <<= 1) {
        int t = (threadIdx.x >= (unsigned)off) ? s[threadIdx.x - off] : 0;
        __syncthreads();
        s[threadIdx.x] += t;
        __syncthreads();
    }
    if (i < n) g_rowptr[i] = s[threadIdx.x] - v;   // exclusive within block
    if (threadIdx.x == 1023) g_bsum[blockIdx.x] = s[1023];
}

__global__ void k_scan2(int nb) {
    if (threadIdx.x == 0 && blockIdx.x == 0) {
        int run = 0;
        for (int b = 0; b < nb; b++) { int t = g_bsum[b]; g_boff[b] = run; run += t; }
    }
}

__global__ void k_scan3(int n, int e) {
    int i = blockIdx.x * 1024 + threadIdx.x;
    if (i < n) {
        int v = g_rowptr[i] + g_boff[blockIdx.x];
        g_rowptr[i] = v;
        g_cursor[i] = v;
    }
    if (i == 0) g_rowptr[n] = e;
}

__global__ void k_fill(const void* eraw, int e) {
    int i = blockIdx.x * blockDim.x + threadIdx.x;
    if (i >= e) return;
    int s, d;
    if (g_flag64) {
        const long long* p = (const long long*)eraw;
        s = (int)p[i];
        d = (int)p[(size_t)e + i];
    } else {
        const int* p = (const int*)eraw;
        s = p[i];
        d = p[e + i];
    }
    int pos = atomicAdd(&g_cursor[d], 1);
    g_col[pos] = s;
}

// ---------------- tf32 tensor-core dual GEMM ----------------
// P = X @ Wrel ; B = X @ Wroot + b_rel, both [n,64]; combined N=128.
// Block: 256 threads / 8 warps, 128-row tile; warp tile 16 rows x 128 cols.
// Xs padded to K+4 floats/row, Ws padded to 136: conflict-free fragment LDS.
template <int K>
__global__ __launch_bounds__(256) void k_gemm_tf32(
    const float* __restrict__ X,
    const float* __restrict__ Wrel,
    const float* __restrict__ Wroot,
    const float* __restrict__ brel,
    int n)
{
    extern __shared__ float sm[];
    float* Xs = sm;                    // [128][K+4]
    float* Ws = sm + 128 * (K + 4);    // [K][136]: cols 0-63 Wrel, 64-127 Wroot
    const float* src = (K == INCH) ? X : g_H;

    int tid  = threadIdx.x;
    int lane = tid & 31;
    int warp = tid >> 5;
    int row0 = blockIdx.x * 128;

    for (int i = tid; i < K * 64; i += 256) {
        int k = i >> 6, c = i & 63;
        Ws[k * 136 + c]      = to_tf32(Wrel[i]);
        Ws[k * 136 + 64 + c] = to_tf32(Wroot[i]);
    }
    for (int i = tid; i < 128 * (K / 4); i += 256) {
        int r = i / (K / 4);
        int kk = (i % (K / 4)) * 4;
        int gr = row0 + r;
        float4 v = make_float4(0.f, 0.f, 0.f, 0.f);
        if (gr < n) v = *(const float4*)(src + (size_t)gr * K + kk);
        float* dst = Xs + r * (K + 4) + kk;
        dst[0] = to_tf32(v.x); dst[1] = to_tf32(v.y);
        dst[2] = to_tf32(v.z); dst[3] = to_tf32(v.w);
    }
    __syncthreads();

    int g   = lane >> 2;   // 0..7
    int tig = lane & 3;    // 0..3

    float c[16][4];
#pragma unroll
    for (int nt = 0; nt < 16; nt++)
#pragma unroll
        for (int j = 0; j < 4; j++) c[nt][j] = 0.f;

    const float* xrow0 = Xs + (warp * 16 + g) * (K + 4);
    const float* xrow1 = xrow0 + 8 * (K + 4);

    for (int k0 = 0; k0 < K; k0 += 8) {
        // A fragment (m16n8k8 tf32 row-major): a0=(g,tig) a1=(g+8,tig) a2=(g,tig+4) a3=(g+8,tig+4)
        uint32_t a0 = __float_as_uint(xrow0[k0 + tig]);
        uint32_t a1 = __float_as_uint(xrow1[k0 + tig]);
        uint32_t a2 = __float_as_uint(xrow0[k0 + tig + 4]);
        uint32_t a3 = __float_as_uint(xrow1[k0 + tig + 4]);
        const float* w0 = Ws + (k0 + tig) * 136 + g;       // b0: k=tig,   n=g
        const float* w1 = Ws + (k0 + tig + 4) * 136 + g;   // b1: k=tig+4, n=g
#pragma unroll
        for (int nt = 0; nt < 16; nt++) {
            uint32_t b0 = __float_as_uint(w0[nt * 8]);
            uint32_t b1 = __float_as_uint(w1[nt * 8]);
            mma_tf32(c[nt], a0, a1, a2, a3, b0, b1);
        }
    }

    // Epilogue: c0,c1 -> row g cols 2*tig,2*tig+1; c2,c3 -> row g+8.
    int gr0 = row0 + warp * 16 + g;
    int gr1 = gr0 + 8;
#pragma unroll
    for (int nt = 0; nt < 16; nt++) {
        if (nt < 8) {
            int col = nt * 8 + tig * 2;
            if (gr0 < n) *(float2*)(g_P + (size_t)gr0 * 64 + col) = make_float2(c[nt][0], c[nt][1]);
            if (gr1 < n) *(float2*)(g_P + (size_t)gr1 * 64 + col) = make_float2(c[nt][2], c[nt][3]);
        } else {
            int col = (nt - 8) * 8 + tig * 2;
            float b0v = brel[col], b1v = brel[col + 1];
            if (gr0 < n) *(float2*)(g_B + (size_t)gr0 * 64 + col) =
                make_float2(c[nt][0] + b0v, c[nt][1] + b1v);
            if (gr1 < n) *(float2*)(g_B + (size_t)gr1 * 64 + col) =
                make_float2(c[nt][2] + b0v, c[nt][3] + b1v);
        }
    }
}

// ---------------- pull aggregation: H[i] = relu(B[i] + sum_{j in N(i)} P[j]) ----
// 16 threads per node, float4 per thread. P (25.6MB) is L2-resident. (R7 config.)
__global__ __launch_bounds__(256) void k_agg(int n) {
    int t = blockIdx.x * blockDim.x + threadIdx.x;
    int gid = t >> 4;
    int l4 = (t & 15) * 4;
    if (gid >= n) return;
    int beg = g_rowptr[gid], end = g_rowptr[gid + 1];
    float4 acc = *(const float4*)(g_B + (size_t)gid * 64 + l4);
    int j = beg;
    for (; j + 3 < end; j += 4) {
        int s0 = g_col[j], s1 = g_col[j + 1], s2 = g_col[j + 2], s3 = g_col[j + 3];
        float4 v0 = *(const float4*)(g_P + (size_t)s0 * 64 + l4);
        float4 v1 = *(const float4*)(g_P + (size_t)s1 * 64 + l4);
        float4 v2 = *(const float4*)(g_P + (size_t)s2 * 64 + l4);
        float4 v3 = *(const float4*)(g_P + (size_t)s3 * 64 + l4);
        acc.x += (v0.x + v1.x) + (v2.x + v3.x);
        acc.y += (v0.y + v1.y) + (v2.y + v3.y);
        acc.z += (v0.z + v1.z) + (v2.z + v3.z);
        acc.w += (v0.w + v1.w) + (v2.w + v3.w);
    }
    for (; j < end; j++) {
        int s = g_col[j];
        float4 v = *(const float4*)(g_P + (size_t)s * 64 + l4);
        acc.x += v.x; acc.y += v.y; acc.z += v.z; acc.w += v.w;
    }
    acc.x = fmaxf(acc.x, 0.f);
    acc.y = fmaxf(acc.y, 0.f);
    acc.z = fmaxf(acc.z, 0.f);
    acc.w = fmaxf(acc.w, 0.f);
    *(float4*)(g_H + (size_t)gid * 64 + l4) = acc;
}

// ---------------- pooling: run-length accumulate (batch is sorted), few atomics --
__global__ __launch_bounds__(256) void k_pool(int n) {
    int d = threadIdx.x & 63;
    int s = threadIdx.x >> 6;      // 0..3
    int start = blockIdx.x * 1024;
    int endn = min(start + 1024, n);
    float acc = 0.f;
    int curg = -1;
    for (int node = start + s; node < endn; node += 4) {
        int g = g_batch[node];
        if (g != curg) {
            if (curg >= 0) atomicAdd(&g_gsum[curg * 64 + d], acc);
            acc = 0.f; curg = g;
        }
        acc += g_H[(size_t)node * 64 + d];
    }
    if (curg >= 0) atomicAdd(&g_gsum[curg * 64 + d], acc);
}

__global__ void k_count(int n) {
    int g = threadIdx.x;           // 64 threads
    if (g >= 64) return;
    int lo0 = 0, hi = n;
    while (lo0 < hi) { int m = (lo0 + hi) >> 1; if (g_batch[m] < g) lo0 = m + 1; else hi = m; }
    int lo1 = lo0; hi = n;
    while (lo1 < hi) { int m = (lo1 + hi) >> 1; if (g_batch[m] < g + 1) lo1 = m + 1; else hi = m; }
    g_gcnt[g] = lo1 - lo0;
}

// ---------------- MLP head ----------------
__global__ __launch_bounds__(256) void k_head(
    const float* __restrict__ W1, const float* __restrict__ b1,
    const float* __restrict__ W2, const float* __restrict__ b2,
    float* __restrict__ out)
{
    __shared__ float pm[64 * 64];
    __shared__ float w1s[64 * 64];
    __shared__ float z[64 * 64];
    int tid = threadIdx.x;
    for (int i = tid; i < 4096; i += 256) {
        int g = i >> 6;
        pm[i] = g_gsum[i] / fmaxf((float)g_gcnt[g], 1.f);
        w1s[i] = W1[i];
    }
    __syncthreads();
    for (int idx = tid; idx < 4096; idx += 256) {
        int g = idx >> 6, jj = idx & 63;
        float s = b1[jj];
#pragma unroll 8
        for (int k = 0; k < 64; k++) s = fmaf(pm[g * 64 + k], w1s[k * 64 + jj], s);
        z[idx] = fmaxf(s, 0.f);
    }
    __syncthreads();
    if (tid < 128) {
        int g = tid >> 1, o = tid & 1;
        float s = b2[o];
#pragma unroll 8
        for (int jj = 0; jj < 64; jj++) s = fmaf(z[g * 64 + jj], W2[jj * 2 + o], s);
        out[g * 2 + o] = s;
    }
}

// ---------------- launch ----------------
extern "C" void kernel_launch(void* const* d_in, const int* in_sizes, int n_in,
                              void* d_out, int out_size)
{
    const float* x      = (const float*)d_in[0];
    const void*  eidx   = d_in[1];
    const void*  batch  = d_in[2];
    const float* wr0    = (const float*)d_in[3];
    const float* br0    = (const float*)d_in[4];
    const float* wroot0 = (const float*)d_in[5];
    const float* wr1    = (const float*)d_in[6];
    const float* br1    = (const float*)d_in[7];
    const float* wroot1 = (const float*)d_in[8];
    const float* wr2    = (const float*)d_in[9];
    const float* br2    = (const float*)d_in[10];
    const float* wroot2 = (const float*)d_in[11];
    const float* hw1    = (const float*)d_in[12];
    const float* hb1    = (const float*)d_in[13];
    const float* hw2    = (const float*)d_in[14];
    const float* hb2    = (const float*)d_in[15];

    int n = in_sizes[0] / INCH;    // 100000
    int e = in_sizes[1] / 2;       // 1600000 (element count is dtype-independent)

    const int SMEM128 = (128 * (INCH + 4) + INCH * 136) * 4;  // 137216
    const int SMEM64  = (128 * (HID + 4) + HID * 136) * 4;    // 69632
    cudaFuncSetAttribute(k_gemm_tf32<INCH>, cudaFuncAttributeMaxDynamicSharedMemorySize, SMEM128);
    cudaFuncSetAttribute(k_gemm_tf32<HID>,  cudaFuncAttributeMaxDynamicSharedMemorySize, SMEM64);

    k_detect<<<1, 256>>>((const int*)eidx);
    k_zero<<<(n + 255) / 256, 256>>>(n);
    k_hist<<<(e + 255) / 256, 256>>>(eidx, e);
    k_convert_batch<<<(n + 255) / 256, 256>>>(batch, n);

    int nb = (n + 1023) / 1024;
    k_scan1<<<nb, 1024>>>(n);
    k_scan2<<<1, 32>>>(nb);
    k_scan3<<<nb, 1024>>>(n, e);
    k_fill<<<(e + 255) / 256, 256>>>(eidx, e);

    int gb = (n + 127) / 128;
    int ab = ((n * 16) + 255) / 256;   // 16 threads per node (R7 config)

    // Layer 0 (K=128 input)
    k_gemm_tf32<INCH><<<gb, 256, SMEM128>>>(x, wr0, wroot0, br0, n);
    k_agg<<<ab, 256>>>(n);
    // Layer 1
    k_gemm_tf32<HID><<<gb, 256, SMEM64>>>(nullptr, wr1, wroot1, br1, n);
    k_agg<<<ab, 256>>>(n);
    // Layer 2
    k_gemm_tf32<HID><<<gb, 256, SMEM64>>>(nullptr, wr2, wroot2, br2, n);
    k_agg<<<ab, 256>>>(n);

    k_pool<<<(n + 1023) / 1024, 256>>>(n);
    k_count<<<1, 64>>>(n);
    k_head<<<1, 256>>>(hw1, hb1, hw2, hb2, (float*)d_out);
}

// round 17
// speedup vs baseline: 1.4870x; 1.0486x over previous
#include <cuda_runtime.h>
#include <cstdint>

#define NMAX 100000
#define EMAX 1600000
#define HID  64
#define INCH 128

// ---------------- scratch (static device globals; no allocation) ----------------
__device__ __align__(256) float g_P[(size_t)NMAX * HID];   // h @ w_rel
__device__ __align__(256) float g_B[(size_t)NMAX * HID];   // h @ w_root + b_rel
__device__ __align__(256) float g_H[(size_t)NMAX * HID];   // activations
__device__ int   g_col[EMAX];          // CSR column (src) array
__device__ int   g_deg[NMAX];
__device__ int   g_rowptr[NMAX + 1];
__device__ int   g_cursor[NMAX];
__device__ int   g_batch[NMAX];
__device__ int   g_bsum[256];
__device__ int   g_boff[256];
__device__ float g_gsum[64 * HID];
__device__ int   g_gcnt[64];
__device__ int   g_flag64;             // 1 if edge_index/batch stored as int64

// ---------------- tf32 helpers ----------------
__device__ __forceinline__ float to_tf32(float x) {
    float r;
    asm("cvt.rna.tf32.f32 %0, %1;" : "=f"(r) : "f"(x));
    return r;
}
__device__ __forceinline__ void mma_tf32(float c[4],
                                         uint32_t a0, uint32_t a1, uint32_t a2, uint32_t a3,
                                         uint32_t b0, uint32_t b1) {
    asm volatile(
        "mma.sync.aligned.m16n8k8.row.col.f32.tf32.tf32.f32 "
        "{%0,%1,%2,%3}, {%4,%5,%6,%7}, {%8,%9}, {%0,%1,%2,%3};"
        : "+f"(c[0]), "+f"(c[1]), "+f"(c[2]), "+f"(c[3])
        : "r"(a0), "r"(a1), "r"(a2), "r"(a3), "r"(b0), "r"(b1));
}

// ---------------- dtype detection ----------------
__global__ void k_detect(const int* e32) {
    __shared__ int any;
    if (threadIdx.x == 0) any = 0;
    __syncthreads();
    int v = 0;
    // int64: every odd 32-bit word (high half) is 0 (values < 1e5).
    // int32: odd words are random node indices — nonzero w.h.p.
    for (int i = threadIdx.x; i < 1024; i += blockDim.x) v |= e32[2 * i + 1];
    if (v) atomicOr(&any, 1);
    __syncthreads();
    if (threadIdx.x == 0) g_flag64 = (any == 0) ? 1 : 0;
}

// ---------------- zero scratch that accumulates ----------------
__global__ void k_zero(int n) {
    int i = blockIdx.x * blockDim.x + threadIdx.x;
    if (i < n) g_deg[i] = 0;
    if (i < 64 * HID) g_gsum[i] = 0.f;
}

// ---------------- degree histogram, 4 edges/thread (vectorized loads) ----------
__global__ void k_hist(const void* eraw, int e) {
    int i4 = (blockIdx.x * blockDim.x + threadIdx.x) * 4;
    if (i4 >= e) return;
    int d0, d1, d2, d3;
    if (g_flag64) {
        const long long* p = (const long long*)eraw + (size_t)e + i4;
        if (i4 + 4 <= e) {
            longlong2 a = *(const longlong2*)p;
            longlong2 b = *(const longlong2*)(p + 2);
            d0 = (int)a.x; d1 = (int)a.y; d2 = (int)b.x; d3 = (int)b.y;
        } else {
            d0 = (int)p[0];
            d1 = (i4 + 1 < e) ? (int)p[1] : -1;
            d2 = (i4 + 2 < e) ? (int)p[2] : -1;
            d3 = -1;
        }
    } else {
        const int* p = (const int*)eraw + e + i4;
        if (i4 + 4 <= e) {
            int4 a = *(const int4*)p;
            d0 = a.x; d1 = a.y; d2 = a.z; d3 = a.w;
        } else {
            d0 = p[0];
            d1 = (i4 + 1 < e) ? p[1] : -1;
            d2 = (i4 + 2 < e) ? p[2] : -1;
            d3 = -1;
        }
    }
    atomicAdd(&g_deg[d0], 1);
    if (d1 >= 0) atomicAdd(&g_deg[d1], 1);
    if (d2 >= 0) atomicAdd(&g_deg[d2], 1);
    if (d3 >= 0) atomicAdd(&g_deg[d3], 1);
}

__global__ void k_convert_batch(const void* braw, int n) {
    int i = blockIdx.x * blockDim.x + threadIdx.x;
    if (i >= n) return;
    g_batch[i] = g_flag64 ? (int)((const long long*)braw)[i] : ((const int*)braw)[i];
}

// ---------------- 3-kernel exclusive scan over degrees ----------------
__global__ void k_scan1(int n) {
    __shared__ int s[1024];
    int i = blockIdx.x * 1024 + threadIdx.x;
    int v = (i < n) ? g_deg[i] : 0;
    s[threadIdx.x] = v;
    __syncthreads();
#pragma unroll
    for (int off = 1; off < 1024; off <<= 1) {
        int t = (threadIdx.x >= (unsigned)off) ? s[threadIdx.x - off] : 0;
        __syncthreads();
        s[threadIdx.x] += t;
        __syncthreads();
    }
    if (i < n) g_rowptr[i] = s[threadIdx.x] - v;   // exclusive within block
    if (threadIdx.x == 1023) g_bsum[blockIdx.x] = s[1023];
}

__global__ void k_scan2(int nb) {
    if (threadIdx.x == 0 && blockIdx.x == 0) {
        int run = 0;
        for (int b = 0; b < nb; b++) { int t = g_bsum[b]; g_boff[b] = run; run += t; }
    }
}

__global__ void k_scan3(int n, int e) {
    int i = blockIdx.x * 1024 + threadIdx.x;
    if (i < n) {
        int v = g_rowptr[i] + g_boff[blockIdx.x];
        g_rowptr[i] = v;
        g_cursor[i] = v;
    }
    if (i == 0) g_rowptr[n] = e;
}

// ---------------- CSR fill, 4 edges/thread (vectorized loads) ----------------
__global__ void k_fill(const void* eraw, int e) {
    int i4 = (blockIdx.x * blockDim.x + threadIdx.x) * 4;
    if (i4 >= e) return;
    int s0, s1, s2, s3, d0, d1, d2, d3;
    int nvalid;
    if (g_flag64) {
        const long long* ps = (const long long*)eraw + i4;
        const long long* pd = (const long long*)eraw + (size_t)e + i4;
        if (i4 + 4 <= e) {
            longlong2 sa = *(const longlong2*)ps;
            longlong2 sb = *(const longlong2*)(ps + 2);
            longlong2 da = *(const longlong2*)pd;
            longlong2 db = *(const longlong2*)(pd + 2);
            s0 = (int)sa.x; s1 = (int)sa.y; s2 = (int)sb.x; s3 = (int)sb.y;
            d0 = (int)da.x; d1 = (int)da.y; d2 = (int)db.x; d3 = (int)db.y;
            nvalid = 4;
        } else {
            nvalid = e - i4;
            s0 = (int)ps[0]; d0 = (int)pd[0];
            s1 = (nvalid > 1) ? (int)ps[1] : 0; d1 = (nvalid > 1) ? (int)pd[1] : 0;
            s2 = (nvalid > 2) ? (int)ps[2] : 0; d2 = (nvalid > 2) ? (int)pd[2] : 0;
            s3 = 0; d3 = 0;
        }
    } else {
        const int* ps = (const int*)eraw + i4;
        const int* pd = (const int*)eraw + e + i4;
        if (i4 + 4 <= e) {
            int4 sa = *(const int4*)ps;
            int4 da = *(const int4*)pd;
            s0 = sa.x; s1 = sa.y; s2 = sa.z; s3 = sa.w;
            d0 = da.x; d1 = da.y; d2 = da.z; d3 = da.w;
            nvalid = 4;
        } else {
            nvalid = e - i4;
            s0 = ps[0]; d0 = pd[0];
            s1 = (nvalid > 1) ? ps[1] : 0; d1 = (nvalid > 1) ? pd[1] : 0;
            s2 = (nvalid > 2) ? ps[2] : 0; d2 = (nvalid > 2) ? pd[2] : 0;
            s3 = 0; d3 = 0;
        }
    }
    {
        int pos = atomicAdd(&g_cursor[d0], 1); g_col[pos] = s0;
    }
    if (nvalid > 1) { int pos = atomicAdd(&g_cursor[d1], 1); g_col[pos] = s1; }
    if (nvalid > 2) { int pos = atomicAdd(&g_cursor[d2], 1); g_col[pos] = s2; }
    if (nvalid > 3) { int pos = atomicAdd(&g_cursor[d3], 1); g_col[pos] = s3; }
}

// ---------------- tf32 tensor-core dual GEMM ----------------
// P = X @ Wrel ; B = X @ Wroot + b_rel, both [n,64]; combined N=128.
// Block: 256 threads / 8 warps, 128-row tile; warp tile 16 rows x 128 cols.
// Xs padded to K+4 floats/row, Ws padded to 136: conflict-free fragment LDS.
template <int K>
__global__ __launch_bounds__(256) void k_gemm_tf32(
    const float* __restrict__ X,
    const float* __restrict__ Wrel,
    const float* __restrict__ Wroot,
    const float* __restrict__ brel,
    int n)
{
    extern __shared__ float sm[];
    float* Xs = sm;                    // [128][K+4]
    float* Ws = sm + 128 * (K + 4);    // [K][136]: cols 0-63 Wrel, 64-127 Wroot
    const float* src = (K == INCH) ? X : g_H;

    int tid  = threadIdx.x;
    int lane = tid & 31;
    int warp = tid >> 5;
    int row0 = blockIdx.x * 128;

    for (int i = tid; i < K * 64; i += 256) {
        int k = i >> 6, c = i & 63;
        Ws[k * 136 + c]      = to_tf32(Wrel[i]);
        Ws[k * 136 + 64 + c] = to_tf32(Wroot[i]);
    }
    for (int i = tid; i < 128 * (K / 4); i += 256) {
        int r = i / (K / 4);
        int kk = (i % (K / 4)) * 4;
        int gr = row0 + r;
        float4 v = make_float4(0.f, 0.f, 0.f, 0.f);
        if (gr < n) v = *(const float4*)(src + (size_t)gr * K + kk);
        float* dst = Xs + r * (K + 4) + kk;
        dst[0] = to_tf32(v.x); dst[1] = to_tf32(v.y);
        dst[2] = to_tf32(v.z); dst[3] = to_tf32(v.w);
    }
    __syncthreads();

    int g   = lane >> 2;   // 0..7
    int tig = lane & 3;    // 0..3

    float c[16][4];
#pragma unroll
    for (int nt = 0; nt < 16; nt++)
#pragma unroll
        for (int j = 0; j < 4; j++) c[nt][j] = 0.f;

    const float* xrow0 = Xs + (warp * 16 + g) * (K + 4);
    const float* xrow1 = xrow0 + 8 * (K + 4);

    for (int k0 = 0; k0 < K; k0 += 8) {
        // A fragment (m16n8k8 tf32 row-major): a0=(g,tig) a1=(g+8,tig) a2=(g,tig+4) a3=(g+8,tig+4)
        uint32_t a0 = __float_as_uint(xrow0[k0 + tig]);
        uint32_t a1 = __float_as_uint(xrow1[k0 + tig]);
        uint32_t a2 = __float_as_uint(xrow0[k0 + tig + 4]);
        uint32_t a3 = __float_as_uint(xrow1[k0 + tig + 4]);
        const float* w0 = Ws + (k0 + tig) * 136 + g;       // b0: k=tig,   n=g
        const float* w1 = Ws + (k0 + tig + 4) * 136 + g;   // b1: k=tig+4, n=g
#pragma unroll
        for (int nt = 0; nt < 16; nt++) {
            uint32_t b0 = __float_as_uint(w0[nt * 8]);
            uint32_t b1 = __float_as_uint(w1[nt * 8]);
            mma_tf32(c[nt], a0, a1, a2, a3, b0, b1);
        }
    }

    // Epilogue: c0,c1 -> row g cols 2*tig,2*tig+1; c2,c3 -> row g+8.
    int gr0 = row0 + warp * 16 + g;
    int gr1 = gr0 + 8;
#pragma unroll
    for (int nt = 0; nt < 16; nt++) {
        if (nt < 8) {
            int col = nt * 8 + tig * 2;
            if (gr0 < n) *(float2*)(g_P + (size_t)gr0 * 64 + col) = make_float2(c[nt][0], c[nt][1]);
            if (gr1 < n) *(float2*)(g_P + (size_t)gr1 * 64 + col) = make_float2(c[nt][2], c[nt][3]);
        } else {
            int col = (nt - 8) * 8 + tig * 2;
            float b0v = brel[col], b1v = brel[col + 1];
            if (gr0 < n) *(float2*)(g_B + (size_t)gr0 * 64 + col) =
                make_float2(c[nt][0] + b0v, c[nt][1] + b1v);
            if (gr1 < n) *(float2*)(g_B + (size_t)gr1 * 64 + col) =
                make_float2(c[nt][2] + b0v, c[nt][3] + b1v);
        }
    }
}

// ---------------- pull aggregation: H[i] = relu(B[i] + sum_{j in N(i)} P[j]) ----
// 16 threads per node, float4 per thread. P (25.6MB) is L2-resident. (R7 config.)
__global__ __launch_bounds__(256) void k_agg(int n) {
    int t = blockIdx.x * blockDim.x + threadIdx.x;
    int gid = t >> 4;
    int l4 = (t & 15) * 4;
    if (gid >= n) return;
    int beg = g_rowptr[gid], end = g_rowptr[gid + 1];
    float4 acc = *(const float4*)(g_B + (size_t)gid * 64 + l4);
    int j = beg;
    for (; j + 3 < end; j += 4) {
        int s0 = g_col[j], s1 = g_col[j + 1], s2 = g_col[j + 2], s3 = g_col[j + 3];
        float4 v0 = *(const float4*)(g_P + (size_t)s0 * 64 + l4);
        float4 v1 = *(const float4*)(g_P + (size_t)s1 * 64 + l4);
        float4 v2 = *(const float4*)(g_P + (size_t)s2 * 64 + l4);
        float4 v3 = *(const float4*)(g_P + (size_t)s3 * 64 + l4);
        acc.x += (v0.x + v1.x) + (v2.x + v3.x);
        acc.y += (v0.y + v1.y) + (v2.y + v3.y);
        acc.z += (v0.z + v1.z) + (v2.z + v3.z);
        acc.w += (v0.w + v1.w) + (v2.w + v3.w);
    }
    for (; j < end; j++) {
        int s = g_col[j];
        float4 v = *(const float4*)(g_P + (size_t)s * 64 + l4);
        acc.x += v.x; acc.y += v.y; acc.z += v.z; acc.w += v.w;
    }
    acc.x = fmaxf(acc.x, 0.f);
    acc.y = fmaxf(acc.y, 0.f);
    acc.z = fmaxf(acc.z, 0.f);
    acc.w = fmaxf(acc.w, 0.f);
    *(float4*)(g_H + (size_t)gid * 64 + l4) = acc;
}

// ---------------- pooling: run-length accumulate (batch is sorted), few atomics --
__global__ __launch_bounds__(256) void k_pool(int n) {
    int d = threadIdx.x & 63;
    int s = threadIdx.x >> 6;      // 0..3
    int start = blockIdx.x * 1024;
    int endn = min(start + 1024, n);
    float acc = 0.f;
    int curg = -1;
    for (int node = start + s; node < endn; node += 4) {
        int g = g_batch[node];
        if (g != curg) {
            if (curg >= 0) atomicAdd(&g_gsum[curg * 64 + d], acc);
            acc = 0.f; curg = g;
        }
        acc += g_H[(size_t)node * 64 + d];
    }
    if (curg >= 0) atomicAdd(&g_gsum[curg * 64 + d], acc);
}

__global__ void k_count(int n) {
    int g = threadIdx.x;           // 64 threads
    if (g >= 64) return;
    int lo0 = 0, hi = n;
    while (lo0 < hi) { int m = (lo0 + hi) >> 1; if (g_batch[m] < g) lo0 = m + 1; else hi = m; }
    int lo1 = lo0; hi = n;
    while (lo1 < hi) { int m = (lo1 + hi) >> 1; if (g_batch[m] < g + 1) lo1 = m + 1; else hi = m; }
    g_gcnt[g] = lo1 - lo0;
}

// ---------------- MLP head ----------------
__global__ __launch_bounds__(256) void k_head(
    const float* __restrict__ W1, const float* __restrict__ b1,
    const float* __restrict__ W2, const float* __restrict__ b2,
    float* __restrict__ out)
{
    __shared__ float pm[64 * 64];
    __shared__ float w1s[64 * 64];
    __shared__ float z[64 * 64];
    int tid = threadIdx.x;
    for (int i = tid; i < 4096; i += 256) {
        int g = i >> 6;
        pm[i] = g_gsum[i] / fmaxf((float)g_gcnt[g], 1.f);
        w1s[i] = W1[i];
    }
    __syncthreads();
    for (int idx = tid; idx < 4096; idx += 256) {
        int g = idx >> 6, jj = idx & 63;
        float s = b1[jj];
#pragma unroll 8
        for (int k = 0; k < 64; k++) s = fmaf(pm[g * 64 + k], w1s[k * 64 + jj], s);
        z[idx] = fmaxf(s, 0.f);
    }
    __syncthreads();
    if (tid < 128) {
        int g = tid >> 1, o = tid & 1;
        float s = b2[o];
#pragma unroll 8
        for (int jj = 0; jj < 64; jj++) s = fmaf(z[g * 64 + jj], W2[jj * 2 + o], s);
        out[g * 2 + o] = s;
    }
}

// ---------------- launch ----------------
extern "C" void kernel_launch(void* const* d_in, const int* in_sizes, int n_in,
                              void* d_out, int out_size)
{
    const float* x      = (const float*)d_in[0];
    const void*  eidx   = d_in[1];
    const void*  batch  = d_in[2];
    const float* wr0    = (const float*)d_in[3];
    const float* br0    = (const float*)d_in[4];
    const float* wroot0 = (const float*)d_in[5];
    const float* wr1    = (const float*)d_in[6];
    const float* br1    = (const float*)d_in[7];
    const float* wroot1 = (const float*)d_in[8];
    const float* wr2    = (const float*)d_in[9];
    const float* br2    = (const float*)d_in[10];
    const float* wroot2 = (const float*)d_in[11];
    const float* hw1    = (const float*)d_in[12];
    const float* hb1    = (const float*)d_in[13];
    const float* hw2    = (const float*)d_in[14];
    const float* hb2    = (const float*)d_in[15];

    int n = in_sizes[0] / INCH;    // 100000
    int e = in_sizes[1] / 2;       // 1600000 (element count is dtype-independent)

    const int SMEM128 = (128 * (INCH + 4) + INCH * 136) * 4;  // 137216
    const int SMEM64  = (128 * (HID + 4) + HID * 136) * 4;    // 69632
    cudaFuncSetAttribute(k_gemm_tf32<INCH>, cudaFuncAttributeMaxDynamicSharedMemorySize, SMEM128);
    cudaFuncSetAttribute(k_gemm_tf32<HID>,  cudaFuncAttributeMaxDynamicSharedMemorySize, SMEM64);

    // Side stream for work independent of the CSR build. Non-blocking so the
    // legacy-stream implicit sync doesn't serialize it; forked/joined with
    // events so graph capture records true parallel branches. Host-side
    // objects only (no device memory); identical work every call.
    static cudaStream_t s1 = nullptr;
    static cudaEvent_t ev_fork = nullptr, ev_join = nullptr;
    if (s1 == nullptr) {
        cudaStreamCreateWithFlags(&s1, cudaStreamNonBlocking);
        cudaEventCreateWithFlags(&ev_fork, cudaEventDisableTiming);
        cudaEventCreateWithFlags(&ev_join, cudaEventDisableTiming);
    }

    int gb = (n + 127) / 128;
    int ab = ((n * 16) + 255) / 256;   // 16 threads per node
    int e4 = (e + 3) / 4;

    k_detect<<<1, 256>>>((const int*)eidx);

    // ---- fork: layer-0 GEMM + batch conversion + graph counts (independent of CSR)
    cudaEventRecord(ev_fork, 0);
    cudaStreamWaitEvent(s1, ev_fork, 0);
    k_gemm_tf32<INCH><<<gb, 256, SMEM128, s1>>>(x, wr0, wroot0, br0, n);
    k_convert_batch<<<(n + 255) / 256, 256, 0, s1>>>(batch, n);
    k_count<<<1, 64, 0, s1>>>(n);
    cudaEventRecord(ev_join, s1);

    // ---- main stream: CSR build
    k_zero<<<(n + 255) / 256, 256>>>(n);
    k_hist<<<(e4 + 255) / 256, 256>>>(eidx, e);
    int nb = (n + 1023) / 1024;
    k_scan1<<<nb, 1024>>>(n);
    k_scan2<<<1, 32>>>(nb);
    k_scan3<<<nb, 1024>>>(n, e);
    k_fill<<<(e4 + 255) / 256, 256>>>(eidx, e);

    // ---- join: agg0 needs both the CSR and layer-0 GEMM outputs
    cudaStreamWaitEvent(0, ev_join, 0);

    k_agg<<<ab, 256>>>(n);
    // Layer 1
    k_gemm_tf32<HID><<<gb, 256, SMEM64>>>(nullptr, wr1, wroot1, br1, n);
    k_agg<<<ab, 256>>>(n);
    // Layer 2
    k_gemm_tf32<HID><<<gb, 256, SMEM64>>>(nullptr, wr2, wroot2, br2, n);
    k_agg<<<ab, 256>>>(n);

    k_pool<<<(n + 1023) / 1024, 256>>>(n);
    k_head<<<1, 256>>>(hw1, hb1, hw2, hb2, (float*)d_out);
}